// round 15
// baseline (speedup 1.0000x reference)
#include <cuda_runtime.h>
#include <cuda_bf16.h>
#include <cstdint>

#define NNODES 100000
#define NEDGES 1600000
#define DF 128
#define NCLS 40
#define TM 128
#define NB_SCAN 98          // ceil(100000/1024)

// ---- smem byte offsets (bf16 matrices: 128x128, 256B rows, swizzled 16B chunks)
#define S_WA_HI 0
#define S_WA_LO 32768
#define S_WB_HI 65536
#define S_WB_LO 98304
#define S_A_HI  131072
#define S_A_LO  163840
#define S_WFC   196608      // 20480 B fp32
#define S_BA    217088      // 512
#define S_BB    217600      // 512
#define S_BSF   218112      // 256
#define S_TOTAL 218368
#define YTLD 130            // y tile stride (floats); y region reuses offset 0

// Scratch (allocation-free rule: __device__ globals)
__device__ float g_h1[NNODES * DF];
__device__ __align__(16) unsigned short g_preh[NNODES * DF];
__device__ __align__(16) unsigned short g_prel[NNODES * DF];
__device__ int   g_csr[NEDGES];
__device__ int   g_deg[NNODES];
__device__ int   g_off[NNODES + 1];
__device__ int   g_cur[NNODES];
__device__ int   g_bsum[NB_SCAN];
// per layer: [waH | waL | wbH | wbL], each 16384 bf16 (swizzled)
__device__ __align__(16) unsigned short g_wcvt[2 * 4 * DF * DF];

// ---------------------------------------------------------------------------
__device__ __forceinline__ uint32_t smem_u32(const void* p) {
    uint32_t a;
    asm("{ .reg .u64 t; cvta.to.shared.u64 t, %1; cvt.u32.u64 %0, t; }"
        : "=r"(a) : "l"(p));
    return a;
}

#define LDMX4(r0, r1, r2, r3, a) \
    asm volatile("ldmatrix.sync.aligned.m8n8.x4.shared.b16 {%0,%1,%2,%3}, [%4];" \
        : "=r"(r0), "=r"(r1), "=r"(r2), "=r"(r3) : "r"(a))
#define LDMX4T(r0, r1, r2, r3, a) \
    asm volatile("ldmatrix.sync.aligned.m8n8.x4.trans.shared.b16 {%0,%1,%2,%3}, [%4];" \
        : "=r"(r0), "=r"(r1), "=r"(r2), "=r"(r3) : "r"(a))
#define MMA(C, a0, a1, a2, a3, b0, b1) \
    asm volatile("mma.sync.aligned.m16n8k16.row.col.f32.bf16.bf16.f32 " \
                 "{%0,%1,%2,%3}, {%4,%5,%6,%7}, {%8,%9}, {%0,%1,%2,%3};" \
        : "+f"((C)[0]), "+f"((C)[1]), "+f"((C)[2]), "+f"((C)[3]) \
        : "r"(a0), "r"(a1), "r"(a2), "r"(a3), "r"(b0), "r"(b1))

__device__ __forceinline__ void cvt_split(float f, unsigned short& h, unsigned short& l) {
    __nv_bfloat16 bh = __float2bfloat16(f);
    float r = f - __bfloat162float(bh);
    __nv_bfloat16 bl = __float2bfloat16(r);
    h = __bfloat16_as_ushort(bh);
    l = __bfloat16_as_ushort(bl);
}

__device__ __forceinline__ bool edges_are_i64(const int* raw) {
    return (raw[1] | raw[3] | raw[5] | raw[7] |
            raw[9] | raw[11] | raw[13] | raw[15]) == 0;
}

// ---------------------------------------------------------------------------
__global__ void zero_int_kernel(int* __restrict__ p, int n) {
    int i = blockIdx.x * blockDim.x + threadIdx.x;
    if (i < n) p[i] = 0;
}

__global__ void hist_kernel(const int* __restrict__ raw, int* __restrict__ deg) {
    bool is64 = edges_are_i64(raw);
    int i = blockIdx.x * blockDim.x + threadIdx.x;
    if (i >= NEDGES) return;
    int d = is64 ? raw[2 * NEDGES + 2 * i] : raw[NEDGES + i];
    atomicAdd(deg + d, 1);
}

// ---- 2-phase device-wide exclusive scan of degrees ----
__global__ void scan_part_kernel(const int* __restrict__ deg,
                                 int* __restrict__ bsum) {
    __shared__ int s[256];
    int b = blockIdx.x, t = threadIdx.x;
    int base = b * 1024 + t * 4;
    int v = 0;
#pragma unroll
    for (int j = 0; j < 4; j++) {
        int idx = base + j;
        if (idx < NNODES) v += deg[idx];
    }
    s[t] = v;
    __syncthreads();
#pragma unroll
    for (int ofs = 128; ofs > 0; ofs >>= 1) {
        if (t < ofs) s[t] += s[t + ofs];
        __syncthreads();
    }
    if (t == 0) bsum[b] = s[0];
}

// scan_write with inlined "tops" prefix: thread 0 sums bsum[0..b-1] (<=97 adds).
__global__ void scan_write_kernel(const int* __restrict__ deg,
                                  const int* __restrict__ bsum,
                                  int* __restrict__ off,
                                  int* __restrict__ cur) {
    __shared__ int s[256];
    __shared__ int sbase;
    int b = blockIdx.x, t = threadIdx.x;
    if (t == 0) {
        int acc = 0;
        for (int i = 0; i < b; i++) acc += __ldg(bsum + i);
        sbase = acc;
    }
    int base = b * 1024 + t * 4;
    int d[4];
    int v = 0;
#pragma unroll
    for (int j = 0; j < 4; j++) {
        int idx = base + j;
        d[j] = (idx < NNODES) ? deg[idx] : 0;
        v += d[j];
    }
    s[t] = v;
    __syncthreads();
#pragma unroll
    for (int ofs = 1; ofs < 256; ofs <<= 1) {
        int u = (t >= ofs) ? s[t - ofs] : 0;
        __syncthreads();
        s[t] += u;
        __syncthreads();
    }
    int run = sbase + s[t] - v;   // exclusive prefix for this thread's chunk
#pragma unroll
    for (int j = 0; j < 4; j++) {
        int idx = base + j;
        if (idx < NNODES) {
            off[idx] = run;
            cur[idx] = run;
            run += d[j];
        }
    }
    if (b == NB_SCAN - 1 && t == 255) off[NNODES] = sbase + s[255];
}

__global__ void scatter_kernel(const int* __restrict__ raw,
                               int* __restrict__ cur,
                               int* __restrict__ csr) {
    bool is64 = edges_are_i64(raw);
    int i = blockIdx.x * blockDim.x + threadIdx.x;
    if (i >= NEDGES) return;
    int s, d;
    if (is64) { s = raw[2 * i]; d = raw[2 * NEDGES + 2 * i]; }
    else      { s = raw[i];     d = raw[NEDGES + i]; }
    int pos = atomicAdd(cur + d, 1);
    csr[pos] = s;
}

// ---------------------------------------------------------------------------
// Weight prep: split fp32 -> bf16 hi/lo, k-major rows (256B), swizzled chunks.
__global__ void prep_w_kernel(const float* __restrict__ w1a, const float* __restrict__ w1b,
                              const float* __restrict__ w2a, const float* __restrict__ w2b,
                              unsigned short* __restrict__ dst) {
    int i = blockIdx.x * blockDim.x + threadIdx.x;
    if (i >= DF * DF) return;
    int k = i >> 7, n = i & 127;
    int sw = (n >> 3) ^ (k & 7);
    int off = k * 128 + sw * 8 + (n & 7);
    const float* srcs[4] = {w1a, w1b, w2a, w2b};
#pragma unroll
    for (int m = 0; m < 4; m++) {
        unsigned short h, l;
        cvt_split(srcs[m][i], h, l);
        unsigned short* b = dst + (m >> 1) * (4 * DF * DF) + (m & 1) * (2 * DF * DF);
        b[off] = h;
        b[DF * DF + off] = l;
    }
}

// ---------------------------------------------------------------------------
// Gather aggregation: fp32 accumulate, bf16 hi/lo split at write.
__global__ void agg_kernel(const float* __restrict__ feat,
                           const float* __restrict__ xin,
                           const int* __restrict__ off,
                           const int* __restrict__ csr,
                           unsigned short* __restrict__ preh,
                           unsigned short* __restrict__ prel) {
    int node = (blockIdx.x * blockDim.x + threadIdx.x) >> 5;
    int lane = threadIdx.x & 31;
    if (node >= NNODES) return;
    int e0 = off[node], e1 = off[node + 1];
    float4 acc = reinterpret_cast<const float4*>(xin + (size_t)node * DF)[lane];
#pragma unroll 1
    for (int e = e0; e < e1; e += 8) {
        int n[8];
        float s[8];
#pragma unroll
        for (int j = 0; j < 8; j++) {
            int idx = e + j;
            n[j] = __ldg(csr + min(idx, e1 - 1));
            s[j] = (idx < e1) ? 1.f : 0.f;
        }
        float4 v[8];
#pragma unroll
        for (int j = 0; j < 8; j++)
            v[j] = *reinterpret_cast<const float4*>(feat + (size_t)n[j] * DF + lane * 4);
#pragma unroll
        for (int j = 0; j < 8; j++) {
            acc.x = fmaf(v[j].x, s[j], acc.x);
            acc.y = fmaf(v[j].y, s[j], acc.y);
            acc.z = fmaf(v[j].z, s[j], acc.z);
            acc.w = fmaf(v[j].w, s[j], acc.w);
        }
    }
    unsigned short h0, l0, h1, l1, h2, l2, h3, l3;
    cvt_split(acc.x, h0, l0);
    cvt_split(acc.y, h1, l1);
    cvt_split(acc.z, h2, l2);
    cvt_split(acc.w, h3, l3);
    uint2 hv = make_uint2((uint32_t)h0 | ((uint32_t)h1 << 16),
                          (uint32_t)h2 | ((uint32_t)h3 << 16));
    uint2 lv = make_uint2((uint32_t)l0 | ((uint32_t)l1 << 16),
                          (uint32_t)l2 | ((uint32_t)l3 << 16));
    *reinterpret_cast<uint2*>(preh + (size_t)node * DF + lane * 4) = hv;
    *reinterpret_cast<uint2*>(prel + (size_t)node * DF + lane * 4) = lv;
}

// ---------------------------------------------------------------------------
// GIN MLP on tensor cores via mma.sync bf16x3 (fp32 accum) — MMA core frozen.
// wb copy pipelined via cp.async behind GEMM1.
__global__ __launch_bounds__(256, 1)
void mlp_mma_kernel(const unsigned short* __restrict__ preh,
                    const unsigned short* __restrict__ prel,
                    const unsigned short* __restrict__ wl,
                    const float* __restrict__ bag, const float* __restrict__ bbg,
                    const float* __restrict__ wfc, const float* __restrict__ bfc,
                    float* __restrict__ out) {
    extern __shared__ __align__(128) unsigned char smem[];
    const uint32_t sb = smem_u32(smem);
    const int t = threadIdx.x;
    const int w = t >> 5, l = t & 31;
    const int row0 = blockIdx.x * TM;
    const bool do_fc = (wfc != nullptr);

    float* sba = (float*)(smem + S_BA);
    float* sbb = (float*)(smem + S_BB);
    float* bsf = (float*)(smem + S_BSF);
    float* wsf = (float*)(smem + S_WFC);
    float* yt  = (float*)smem;

    // wa (64KB) synchronous; wb (64KB) via cp.async (waited after GEMM1)
    {
        const uint4* s4 = (const uint4*)wl;
        uint4* d4 = (uint4*)smem;
#pragma unroll
        for (int i = 0; i < 16; i++) d4[t + i * 256] = s4[t + i * 256];
        const char* gsrc = (const char*)wl + 65536;
#pragma unroll
        for (int i = 0; i < 16; i++) {
            uint32_t daddr = sb + (uint32_t)S_WB_HI + (uint32_t)(t * 16 + i * 4096);
            asm volatile("cp.async.cg.shared.global [%0], [%1], 16;"
                         :: "r"(daddr), "l"(gsrc + t * 16 + i * 4096) : "memory");
        }
        asm volatile("cp.async.commit_group;" ::: "memory");
        if (t < 128) sba[t] = bag[t];
        else         sbb[t - 128] = bbg[t - 128];
        if (do_fc) {
            const uint4* f4 = (const uint4*)wfc;
            uint4* w4 = (uint4*)(smem + S_WFC);
            for (int i = t; i < DF * NCLS / 4; i += 256) w4[i] = f4[i];
            if (t < NCLS) bsf[t] = bfc[t];
        }
    }

    // A tile: pure 16B-chunk copy into swizzled smem (no conversion)
#pragma unroll 1
    for (int i = 0; i < 8; i++) {
        int u = t + (i << 8);          // 0..2047
        int row = u >> 4, ch = u & 15;
        int gr = row0 + row;
        uint4 vh = make_uint4(0, 0, 0, 0), vl = vh;
        if (gr < NNODES) {
            vh = __ldg((const uint4*)(preh + (size_t)gr * DF + ch * 8));
            vl = __ldg((const uint4*)(prel + (size_t)gr * DF + ch * 8));
        }
        uint32_t off = (uint32_t)row * 256u + (uint32_t)((ch ^ (row & 7)) << 4);
        *(uint4*)(smem + S_A_HI + off) = vh;
        *(uint4*)(smem + S_A_LO + off) = vl;
    }
    __syncthreads();

    // lane constants for ldmatrix addressing
    const uint32_t aRow  = (uint32_t)(16 * w + (l & 7) + ((l >> 3) & 1) * 8);
    const uint32_t aXor  = (uint32_t)(l & 7);
    const uint32_t aHalf = (uint32_t)(l >> 4);
    const uint32_t bKloc = (uint32_t)((l & 7) + ((l >> 3) & 1) * 8);
    const int er = l >> 2;          // acc row-in-16 (0..7)
    const int ec = 2 * (l & 3);     // acc col pair base

    float c[16][4];

#define RUN_GEMM(WHI, WLO)                                                     \
    {                                                                          \
        _Pragma("unroll")                                                      \
        for (int j = 0; j < 16; j++)                                           \
            _Pragma("unroll")                                                  \
            for (int q = 0; q < 4; q++) c[j][q] = 0.f;                         \
        _Pragma("unroll 1")                                                    \
        for (int s = 0; s < 8; s++) {                                          \
            uint32_t chA = (uint32_t)(2 * s) + aHalf;                          \
            uint32_t aoff = aRow * 256u + ((chA ^ aXor) << 4);                 \
            uint32_t ah0, ah1, ah2, ah3, al0, al1, al2, al3;                   \
            LDMX4(ah0, ah1, ah2, ah3, sb + S_A_HI + aoff);                     \
            LDMX4(al0, al1, al2, al3, sb + S_A_LO + aoff);                     \
            uint32_t bRowOff = ((uint32_t)(16 * s) + bKloc) * 256u;            \
            _Pragma("unroll")                                                  \
            for (int j2 = 0; j2 < 8; j2++) {                                   \
                uint32_t chB = (uint32_t)(2 * j2) + aHalf;                     \
                uint32_t swb = bRowOff + ((chB ^ aXor) << 4);                  \
                uint32_t bh0, bh1, bh2, bh3, bl0, bl1, bl2, bl3;               \
                LDMX4T(bh0, bh1, bh2, bh3, sb + (WHI) + swb);                  \
                LDMX4T(bl0, bl1, bl2, bl3, sb + (WLO) + swb);                  \
                MMA(c[2 * j2],     ah0, ah1, ah2, ah3, bh0, bh1);              \
                MMA(c[2 * j2],     ah0, ah1, ah2, ah3, bl0, bl1);              \
                MMA(c[2 * j2],     al0, al1, al2, al3, bh0, bh1);              \
                MMA(c[2 * j2 + 1], ah0, ah1, ah2, ah3, bh2, bh3);              \
                MMA(c[2 * j2 + 1], ah0, ah1, ah2, ah3, bl2, bl3);              \
                MMA(c[2 * j2 + 1], al0, al1, al2, al3, bh2, bh3);              \
            }                                                                  \
        }                                                                      \
    }

    // ---- GEMM 1: h = relu(A @ Wa + ba) ----
    RUN_GEMM(S_WA_HI, S_WA_LO)
    __syncthreads();   // everyone done reading A tiles
#pragma unroll
    for (int j = 0; j < 16; j++) {
#pragma unroll
        for (int hf = 0; hf < 2; hf++) {
            int row = 16 * w + er + hf * 8;
            int col = 8 * j + ec;
            float f0 = fmaxf(c[j][2 * hf]     + sba[col],     0.f);
            float f1 = fmaxf(c[j][2 * hf + 1] + sba[col + 1], 0.f);
            unsigned short h0, l0, h1, l1;
            cvt_split(f0, h0, l0);
            cvt_split(f1, h1, l1);
            uint32_t off = (uint32_t)row * 256u + (uint32_t)((j ^ er) << 4)
                           + (uint32_t)(ec * 2);
            *(uint32_t*)(smem + S_A_HI + off) = (uint32_t)h0 | ((uint32_t)h1 << 16);
            *(uint32_t*)(smem + S_A_LO + off) = (uint32_t)l0 | ((uint32_t)l1 << 16);
        }
    }
    asm volatile("cp.async.wait_group 0;" ::: "memory");
    __syncthreads();

    // ---- GEMM 2: y = relu(h @ Wb + bb) ----
    RUN_GEMM(S_WB_HI, S_WB_LO)

    if (!do_fc) {
#pragma unroll
        for (int j = 0; j < 16; j++)
#pragma unroll
            for (int hf = 0; hf < 2; hf++) {
                int row = 16 * w + er + hf * 8;
                int gr = row0 + row;
                if (gr >= NNODES) continue;
                int col = 8 * j + ec;
                float2 v = make_float2(fmaxf(c[j][2 * hf]     + sbb[col],     0.f),
                                       fmaxf(c[j][2 * hf + 1] + sbb[col + 1], 0.f));
                *(float2*)(out + (size_t)gr * DF + col) = v;
            }
        return;
    }

    // ---- FC + log_softmax epilogue ----
    __syncthreads();   // all GEMM2 smem reads done (y overlaps weight regions)
#pragma unroll
    for (int j = 0; j < 16; j++)
#pragma unroll
        for (int hf = 0; hf < 2; hf++) {
            int row = 16 * w + er + hf * 8;
            int col = 8 * j + ec;
            float2 v = make_float2(fmaxf(c[j][2 * hf]     + sbb[col],     0.f),
                                   fmaxf(c[j][2 * hf + 1] + sbb[col + 1], 0.f));
            *(float2*)(yt + row * YTLD + col) = v;
        }
    __syncthreads();

    // Thread t -> row r = t>>1, half = t&1 (20 classes each).
    {
        const int r = t >> 1;
        const int half = t & 1;
        const int cb = half * 20;
        float lg[20];
#pragma unroll
        for (int j = 0; j < 20; j++) lg[j] = bsf[cb + j];
#pragma unroll 4
        for (int k = 0; k < DF; k++) {
            float a = yt[r * YTLD + k];
            const float* wr = &wsf[k * NCLS + cb];
#pragma unroll
            for (int j = 0; j < 20; j++) lg[j] += a * wr[j];
        }
        float m = -1e30f;
#pragma unroll
        for (int j = 0; j < 20; j++) m = fmaxf(m, lg[j]);
        m = fmaxf(m, __shfl_xor_sync(0xffffffffu, m, 1));
        float s = 0.f;
#pragma unroll
        for (int j = 0; j < 20; j++) s += expf(lg[j] - m);
        s += __shfl_xor_sync(0xffffffffu, s, 1);
        float ls = logf(s) + m;
        int gr = row0 + r;
        if (gr < NNODES) {
#pragma unroll
            for (int q = 0; q < 5; q++)
                *(float4*)(out + (size_t)gr * NCLS + cb + q * 4) =
                    make_float4(lg[q * 4] - ls, lg[q * 4 + 1] - ls,
                                lg[q * 4 + 2] - ls, lg[q * 4 + 3] - ls);
        }
    }
}

// ---------------------------------------------------------------------------
extern "C" void kernel_launch(void* const* d_in, const int* in_sizes, int n_in,
                              void* d_out, int out_size) {
    const float* x        = (const float*)d_in[0];
    const int*   ei_raw   = (const int*)d_in[1];
    const float* w1a      = (const float*)d_in[2];
    const float* b1a      = (const float*)d_in[3];
    const float* w1b      = (const float*)d_in[4];
    const float* b1b      = (const float*)d_in[5];
    const float* w2a      = (const float*)d_in[6];
    const float* b2a      = (const float*)d_in[7];
    const float* w2b      = (const float*)d_in[8];
    const float* b2b      = (const float*)d_in[9];
    const float* wfc      = (const float*)d_in[10];
    const float* bfc      = (const float*)d_in[11];
    float* out            = (float*)d_out;

    float *h1;
    unsigned short *preh, *prel, *wcvt;
    int *csr, *deg, *off, *cur, *bsum;
    cudaGetSymbolAddress((void**)&h1, g_h1);
    cudaGetSymbolAddress((void**)&preh, g_preh);
    cudaGetSymbolAddress((void**)&prel, g_prel);
    cudaGetSymbolAddress((void**)&csr, g_csr);
    cudaGetSymbolAddress((void**)&deg, g_deg);
    cudaGetSymbolAddress((void**)&off, g_off);
    cudaGetSymbolAddress((void**)&cur, g_cur);
    cudaGetSymbolAddress((void**)&bsum, g_bsum);
    cudaGetSymbolAddress((void**)&wcvt, g_wcvt);

    cudaFuncSetAttribute(mlp_mma_kernel,
                         cudaFuncAttributeMaxDynamicSharedMemorySize, S_TOTAL);

    const int egrid = (NEDGES + 255) / 256;
    const int ngrid = (NNODES + 255) / 256;
    const int agrid = (int)(((long long)NNODES * 32 + 255) / 256);
    const int mgrid = (NNODES + TM - 1) / TM;

    // --- CSR build + weight prep ---
    zero_int_kernel<<<ngrid, 256>>>(deg, NNODES);
    hist_kernel<<<egrid, 256>>>(ei_raw, deg);
    prep_w_kernel<<<(DF * DF + 255) / 256, 256>>>(w1a, w1b, w2a, w2b, wcvt);
    scan_part_kernel<<<NB_SCAN, 256>>>(deg, bsum);
    scan_write_kernel<<<NB_SCAN, 256>>>(deg, bsum, off, cur);
    scatter_kernel<<<egrid, 256>>>(ei_raw, cur, csr);

    // Layer 1
    agg_kernel<<<agrid, 256>>>(x, x, off, csr, preh, prel);
    mlp_mma_kernel<<<mgrid, 256, S_TOTAL>>>(preh, prel, wcvt, b1a, b1b,
                                            nullptr, nullptr, h1);
    // Layer 2 (+ fused FC/log_softmax)
    agg_kernel<<<agrid, 256>>>(h1, h1, off, csr, preh, prel);
    mlp_mma_kernel<<<mgrid, 256, S_TOTAL>>>(preh, prel, wcvt + 4 * DF * DF, b2a, b2b,
                                            wfc, bfc, out);
}

// round 16
// speedup vs baseline: 1.1501x; 1.1501x over previous
#include <cuda_runtime.h>
#include <cuda_bf16.h>
#include <cstdint>

#define NNODES 100000
#define NEDGES 1600000
#define DF 128
#define NCLS 40
#define TM 128
#define NB_SCAN 98          // ceil(100000/1024)

// ---- smem byte offsets (bf16 matrices: 128x128, 256B rows, swizzled 16B chunks)
#define S_WA_HI 0
#define S_WA_LO 32768
#define S_WB_HI 65536
#define S_WB_LO 98304
#define S_A_HI  131072
#define S_A_LO  163840
#define S_WFC   196608      // 20480 B fp32
#define S_BA    217088      // 512
#define S_BB    217600      // 512
#define S_BSF   218112      // 256
#define S_TOTAL 218368
#define YTLD 130            // y tile stride (floats); y region reuses offset 0

// Scratch (allocation-free rule: __device__ globals)
__device__ float g_h1[NNODES * DF];
__device__ __align__(16) unsigned short g_preh[NNODES * DF];
__device__ __align__(16) unsigned short g_prel[NNODES * DF];
__device__ int   g_csr[NEDGES];
__device__ int   g_deg[NNODES];
__device__ int   g_off[NNODES + 1];
__device__ int   g_cur[NNODES];
__device__ int   g_bsum[NB_SCAN];
// per layer: [waH | waL | wbH | wbL], each 16384 bf16 (swizzled)
__device__ __align__(16) unsigned short g_wcvt[2 * 4 * DF * DF];

// ---------------------------------------------------------------------------
__device__ __forceinline__ uint32_t smem_u32(const void* p) {
    uint32_t a;
    asm("{ .reg .u64 t; cvta.to.shared.u64 t, %1; cvt.u32.u64 %0, t; }"
        : "=r"(a) : "l"(p));
    return a;
}

#define LDMX4(r0, r1, r2, r3, a) \
    asm volatile("ldmatrix.sync.aligned.m8n8.x4.shared.b16 {%0,%1,%2,%3}, [%4];" \
        : "=r"(r0), "=r"(r1), "=r"(r2), "=r"(r3) : "r"(a))
#define LDMX4T(r0, r1, r2, r3, a) \
    asm volatile("ldmatrix.sync.aligned.m8n8.x4.trans.shared.b16 {%0,%1,%2,%3}, [%4];" \
        : "=r"(r0), "=r"(r1), "=r"(r2), "=r"(r3) : "r"(a))
#define MMA(C, a0, a1, a2, a3, b0, b1) \
    asm volatile("mma.sync.aligned.m16n8k16.row.col.f32.bf16.bf16.f32 " \
                 "{%0,%1,%2,%3}, {%4,%5,%6,%7}, {%8,%9}, {%0,%1,%2,%3};" \
        : "+f"((C)[0]), "+f"((C)[1]), "+f"((C)[2]), "+f"((C)[3]) \
        : "r"(a0), "r"(a1), "r"(a2), "r"(a3), "r"(b0), "r"(b1))

__device__ __forceinline__ void cvt_split(float f, unsigned short& h, unsigned short& l) {
    __nv_bfloat16 bh = __float2bfloat16(f);
    float r = f - __bfloat162float(bh);
    __nv_bfloat16 bl = __float2bfloat16(r);
    h = __bfloat16_as_ushort(bh);
    l = __bfloat16_as_ushort(bl);
}

__device__ __forceinline__ bool edges_are_i64(const int* raw) {
    return (raw[1] | raw[3] | raw[5] | raw[7] |
            raw[9] | raw[11] | raw[13] | raw[15]) == 0;
}

// ---------------------------------------------------------------------------
// Weight prep (launch 0): split fp32 -> bf16 hi/lo swizzled; also zeroes deg.
__global__ void prep_w_kernel(const float* __restrict__ w1a, const float* __restrict__ w1b,
                              const float* __restrict__ w2a, const float* __restrict__ w2b,
                              unsigned short* __restrict__ dst,
                              int* __restrict__ deg) {
    int i = blockIdx.x * blockDim.x + threadIdx.x;
    for (int j = i; j < NNODES; j += 16384) deg[j] = 0;
    if (i >= DF * DF) return;
    int k = i >> 7, n = i & 127;
    int sw = (n >> 3) ^ (k & 7);
    int off = k * 128 + sw * 8 + (n & 7);
    const float* srcs[4] = {w1a, w1b, w2a, w2b};
#pragma unroll
    for (int m = 0; m < 4; m++) {
        unsigned short h, l;
        cvt_split(srcs[m][i], h, l);
        unsigned short* b = dst + (m >> 1) * (4 * DF * DF) + (m & 1) * (2 * DF * DF);
        b[off] = h;
        b[DF * DF + off] = l;
    }
}

__global__ void hist_kernel(const int* __restrict__ raw, int* __restrict__ deg) {
    bool is64 = edges_are_i64(raw);
    int i = blockIdx.x * blockDim.x + threadIdx.x;
    if (i >= NEDGES) return;
    int d = is64 ? raw[2 * NEDGES + 2 * i] : raw[NEDGES + i];
    atomicAdd(deg + d, 1);
}

// ---- 2-phase device-wide exclusive scan of degrees ----
__global__ void scan_part_kernel(const int* __restrict__ deg,
                                 int* __restrict__ bsum) {
    __shared__ int s[256];
    int b = blockIdx.x, t = threadIdx.x;
    int base = b * 1024 + t * 4;
    int v = 0;
#pragma unroll
    for (int j = 0; j < 4; j++) {
        int idx = base + j;
        if (idx < NNODES) v += deg[idx];
    }
    s[t] = v;
    __syncthreads();
#pragma unroll
    for (int ofs = 128; ofs > 0; ofs >>= 1) {
        if (t < ofs) s[t] += s[t + ofs];
        __syncthreads();
    }
    if (t == 0) bsum[b] = s[0];
}

// scan_write with inlined "tops" prefix: thread 0 sums bsum[0..b-1] (<=97 adds).
__global__ void scan_write_kernel(const int* __restrict__ deg,
                                  const int* __restrict__ bsum,
                                  int* __restrict__ off,
                                  int* __restrict__ cur) {
    __shared__ int s[256];
    __shared__ int sbase;
    int b = blockIdx.x, t = threadIdx.x;
    if (t == 0) {
        int acc = 0;
        for (int i = 0; i < b; i++) acc += __ldg(bsum + i);
        sbase = acc;
    }
    int base = b * 1024 + t * 4;
    int d[4];
    int v = 0;
#pragma unroll
    for (int j = 0; j < 4; j++) {
        int idx = base + j;
        d[j] = (idx < NNODES) ? deg[idx] : 0;
        v += d[j];
    }
    s[t] = v;
    __syncthreads();
#pragma unroll
    for (int ofs = 1; ofs < 256; ofs <<= 1) {
        int u = (t >= ofs) ? s[t - ofs] : 0;
        __syncthreads();
        s[t] += u;
        __syncthreads();
    }
    int run = sbase + s[t] - v;   // exclusive prefix for this thread's chunk
#pragma unroll
    for (int j = 0; j < 4; j++) {
        int idx = base + j;
        if (idx < NNODES) {
            off[idx] = run;
            cur[idx] = run;
            run += d[j];
        }
    }
    if (b == NB_SCAN - 1 && t == 255) off[NNODES] = sbase + s[255];
}

__global__ void scatter_kernel(const int* __restrict__ raw,
                               int* __restrict__ cur,
                               int* __restrict__ csr) {
    bool is64 = edges_are_i64(raw);
    int i = blockIdx.x * blockDim.x + threadIdx.x;
    if (i >= NEDGES) return;
    int s, d;
    if (is64) { s = raw[2 * i]; d = raw[2 * NEDGES + 2 * i]; }
    else      { s = raw[i];     d = raw[NEDGES + i]; }
    int pos = atomicAdd(cur + d, 1);
    csr[pos] = s;
}

// ---------------------------------------------------------------------------
// Gather aggregation: fp32 accumulate, bf16 hi/lo split at write.
__global__ void agg_kernel(const float* __restrict__ feat,
                           const float* __restrict__ xin,
                           const int* __restrict__ off,
                           const int* __restrict__ csr,
                           unsigned short* __restrict__ preh,
                           unsigned short* __restrict__ prel) {
    int node = (blockIdx.x * blockDim.x + threadIdx.x) >> 5;
    int lane = threadIdx.x & 31;
    if (node >= NNODES) return;
    int e0 = off[node], e1 = off[node + 1];
    float4 acc = reinterpret_cast<const float4*>(xin + (size_t)node * DF)[lane];
#pragma unroll 1
    for (int e = e0; e < e1; e += 8) {
        int n[8];
        float s[8];
#pragma unroll
        for (int j = 0; j < 8; j++) {
            int idx = e + j;
            n[j] = __ldg(csr + min(idx, e1 - 1));
            s[j] = (idx < e1) ? 1.f : 0.f;
        }
        float4 v[8];
#pragma unroll
        for (int j = 0; j < 8; j++)
            v[j] = *reinterpret_cast<const float4*>(feat + (size_t)n[j] * DF + lane * 4);
#pragma unroll
        for (int j = 0; j < 8; j++) {
            acc.x = fmaf(v[j].x, s[j], acc.x);
            acc.y = fmaf(v[j].y, s[j], acc.y);
            acc.z = fmaf(v[j].z, s[j], acc.z);
            acc.w = fmaf(v[j].w, s[j], acc.w);
        }
    }
    unsigned short h0, l0, h1, l1, h2, l2, h3, l3;
    cvt_split(acc.x, h0, l0);
    cvt_split(acc.y, h1, l1);
    cvt_split(acc.z, h2, l2);
    cvt_split(acc.w, h3, l3);
    uint2 hv = make_uint2((uint32_t)h0 | ((uint32_t)h1 << 16),
                          (uint32_t)h2 | ((uint32_t)h3 << 16));
    uint2 lv = make_uint2((uint32_t)l0 | ((uint32_t)l1 << 16),
                          (uint32_t)l2 | ((uint32_t)l3 << 16));
    *reinterpret_cast<uint2*>(preh + (size_t)node * DF + lane * 4) = hv;
    *reinterpret_cast<uint2*>(prel + (size_t)node * DF + lane * 4) = lv;
}

// ---------------------------------------------------------------------------
// GIN MLP on tensor cores via mma.sync bf16x3 (fp32 accum) — MMA core frozen.
// Startup fully async: group0 = {wa, A tile}, group1 = {wb} (waited post-GEMM1).
__global__ __launch_bounds__(256, 1)
void mlp_mma_kernel(const unsigned short* __restrict__ preh,
                    const unsigned short* __restrict__ prel,
                    const unsigned short* __restrict__ wl,
                    const float* __restrict__ bag, const float* __restrict__ bbg,
                    const float* __restrict__ wfc, const float* __restrict__ bfc,
                    float* __restrict__ out) {
    extern __shared__ __align__(128) unsigned char smem[];
    const uint32_t sb = smem_u32(smem);
    const int t = threadIdx.x;
    const int w = t >> 5, l = t & 31;
    const int row0 = blockIdx.x * TM;
    const bool do_fc = (wfc != nullptr);

    float* sba = (float*)(smem + S_BA);
    float* sbb = (float*)(smem + S_BB);
    float* bsf = (float*)(smem + S_BSF);
    float* wsf = (float*)(smem + S_WFC);
    float* yt  = (float*)smem;

    // ---- group 0: wa (64KB) + A tile (64KB, zfill OOB) ----
    {
        const char* gwa = (const char*)wl;
#pragma unroll
        for (int i = 0; i < 16; i++) {
            uint32_t daddr = sb + (uint32_t)(t * 16 + i * 4096);
            asm volatile("cp.async.cg.shared.global [%0], [%1], 16;"
                         :: "r"(daddr), "l"(gwa + t * 16 + i * 4096) : "memory");
        }
#pragma unroll 1
        for (int i = 0; i < 8; i++) {
            int u = t + (i << 8);          // 0..2047
            int row = u >> 4, ch = u & 15;
            int gr = row0 + row;
            bool ok = gr < NNODES;
            int gro = ok ? gr : 0;
            uint32_t srcsz = ok ? 16u : 0u;
            uint32_t off = (uint32_t)row * 256u + (uint32_t)((ch ^ (row & 7)) << 4);
            asm volatile("cp.async.cg.shared.global [%0], [%1], 16, %2;"
                         :: "r"(sb + (uint32_t)S_A_HI + off),
                            "l"(preh + (size_t)gro * DF + ch * 8), "r"(srcsz) : "memory");
            asm volatile("cp.async.cg.shared.global [%0], [%1], 16, %2;"
                         :: "r"(sb + (uint32_t)S_A_LO + off),
                            "l"(prel + (size_t)gro * DF + ch * 8), "r"(srcsz) : "memory");
        }
        asm volatile("cp.async.commit_group;" ::: "memory");
    }
    // ---- group 1: wb (64KB) ----
    {
        const char* gwb = (const char*)wl + 65536;
#pragma unroll
        for (int i = 0; i < 16; i++) {
            uint32_t daddr = sb + (uint32_t)S_WB_HI + (uint32_t)(t * 16 + i * 4096);
            asm volatile("cp.async.cg.shared.global [%0], [%1], 16;"
                         :: "r"(daddr), "l"(gwb + t * 16 + i * 4096) : "memory");
        }
        asm volatile("cp.async.commit_group;" ::: "memory");
    }
    // biases (+ fc weights) — small synchronous loads
    {
        if (t < 128) sba[t] = bag[t];
        else         sbb[t - 128] = bbg[t - 128];
        if (do_fc) {
            const uint4* f4 = (const uint4*)wfc;
            uint4* w4 = (uint4*)(smem + S_WFC);
            for (int i = t; i < DF * NCLS / 4; i += 256) w4[i] = f4[i];
            if (t < NCLS) bsf[t] = bfc[t];
        }
    }
    asm volatile("cp.async.wait_group 1;" ::: "memory");   // group0 (wa+A) done
    __syncthreads();

    // lane constants for ldmatrix addressing
    const uint32_t aRow  = (uint32_t)(16 * w + (l & 7) + ((l >> 3) & 1) * 8);
    const uint32_t aXor  = (uint32_t)(l & 7);
    const uint32_t aHalf = (uint32_t)(l >> 4);
    const uint32_t bKloc = (uint32_t)((l & 7) + ((l >> 3) & 1) * 8);
    const int er = l >> 2;          // acc row-in-16 (0..7)
    const int ec = 2 * (l & 3);     // acc col pair base

    float c[16][4];

#define RUN_GEMM(WHI, WLO)                                                     \
    {                                                                          \
        _Pragma("unroll")                                                      \
        for (int j = 0; j < 16; j++)                                           \
            _Pragma("unroll")                                                  \
            for (int q = 0; q < 4; q++) c[j][q] = 0.f;                         \
        _Pragma("unroll 1")                                                    \
        for (int s = 0; s < 8; s++) {                                          \
            uint32_t chA = (uint32_t)(2 * s) + aHalf;                          \
            uint32_t aoff = aRow * 256u + ((chA ^ aXor) << 4);                 \
            uint32_t ah0, ah1, ah2, ah3, al0, al1, al2, al3;                   \
            LDMX4(ah0, ah1, ah2, ah3, sb + S_A_HI + aoff);                     \
            LDMX4(al0, al1, al2, al3, sb + S_A_LO + aoff);                     \
            uint32_t bRowOff = ((uint32_t)(16 * s) + bKloc) * 256u;            \
            _Pragma("unroll")                                                  \
            for (int j2 = 0; j2 < 8; j2++) {                                   \
                uint32_t chB = (uint32_t)(2 * j2) + aHalf;                     \
                uint32_t swb = bRowOff + ((chB ^ aXor) << 4);                  \
                uint32_t bh0, bh1, bh2, bh3, bl0, bl1, bl2, bl3;               \
                LDMX4T(bh0, bh1, bh2, bh3, sb + (WHI) + swb);                  \
                LDMX4T(bl0, bl1, bl2, bl3, sb + (WLO) + swb);                  \
                MMA(c[2 * j2],     ah0, ah1, ah2, ah3, bh0, bh1);              \
                MMA(c[2 * j2],     ah0, ah1, ah2, ah3, bl0, bl1);              \
                MMA(c[2 * j2],     al0, al1, al2, al3, bh0, bh1);              \
                MMA(c[2 * j2 + 1], ah0, ah1, ah2, ah3, bh2, bh3);              \
                MMA(c[2 * j2 + 1], ah0, ah1, ah2, ah3, bl2, bl3);              \
                MMA(c[2 * j2 + 1], al0, al1, al2, al3, bh2, bh3);              \
            }                                                                  \
        }                                                                      \
    }

    // ---- GEMM 1: h = relu(A @ Wa + ba) ----
    RUN_GEMM(S_WA_HI, S_WA_LO)
    __syncthreads();   // everyone done reading A tiles
#pragma unroll
    for (int j = 0; j < 16; j++) {
#pragma unroll
        for (int hf = 0; hf < 2; hf++) {
            int row = 16 * w + er + hf * 8;
            int col = 8 * j + ec;
            float f0 = fmaxf(c[j][2 * hf]     + sba[col],     0.f);
            float f1 = fmaxf(c[j][2 * hf + 1] + sba[col + 1], 0.f);
            unsigned short h0, l0, h1, l1;
            cvt_split(f0, h0, l0);
            cvt_split(f1, h1, l1);
            uint32_t off = (uint32_t)row * 256u + (uint32_t)((j ^ er) << 4)
                           + (uint32_t)(ec * 2);
            *(uint32_t*)(smem + S_A_HI + off) = (uint32_t)h0 | ((uint32_t)h1 << 16);
            *(uint32_t*)(smem + S_A_LO + off) = (uint32_t)l0 | ((uint32_t)l1 << 16);
        }
    }
    asm volatile("cp.async.wait_group 0;" ::: "memory");
    __syncthreads();

    // ---- GEMM 2: y = relu(h @ Wb + bb) ----
    RUN_GEMM(S_WB_HI, S_WB_LO)

    if (!do_fc) {
#pragma unroll
        for (int j = 0; j < 16; j++)
#pragma unroll
            for (int hf = 0; hf < 2; hf++) {
                int row = 16 * w + er + hf * 8;
                int gr = row0 + row;
                if (gr >= NNODES) continue;
                int col = 8 * j + ec;
                float2 v = make_float2(fmaxf(c[j][2 * hf]     + sbb[col],     0.f),
                                       fmaxf(c[j][2 * hf + 1] + sbb[col + 1], 0.f));
                *(float2*)(out + (size_t)gr * DF + col) = v;
            }
        return;
    }

    // ---- FC + log_softmax epilogue ----
    __syncthreads();   // all GEMM2 smem reads done (y overlaps weight regions)
#pragma unroll
    for (int j = 0; j < 16; j++)
#pragma unroll
        for (int hf = 0; hf < 2; hf++) {
            int row = 16 * w + er + hf * 8;
            int col = 8 * j + ec;
            float2 v = make_float2(fmaxf(c[j][2 * hf]     + sbb[col],     0.f),
                                   fmaxf(c[j][2 * hf + 1] + sbb[col + 1], 0.f));
            *(float2*)(yt + row * YTLD + col) = v;
        }
    __syncthreads();

    // Thread t -> row r = t>>1, half = t&1 (20 classes each).
    {
        const int r = t >> 1;
        const int half = t & 1;
        const int cb = half * 20;
        float lg[20];
#pragma unroll
        for (int j = 0; j < 20; j++) lg[j] = bsf[cb + j];
#pragma unroll 4
        for (int k = 0; k < DF; k++) {
            float a = yt[r * YTLD + k];
            const float* wr = &wsf[k * NCLS + cb];
#pragma unroll
            for (int j = 0; j < 20; j++) lg[j] += a * wr[j];
        }
        float m = -1e30f;
#pragma unroll
        for (int j = 0; j < 20; j++) m = fmaxf(m, lg[j]);
        m = fmaxf(m, __shfl_xor_sync(0xffffffffu, m, 1));
        float s = 0.f;
#pragma unroll
        for (int j = 0; j < 20; j++) s += expf(lg[j] - m);
        s += __shfl_xor_sync(0xffffffffu, s, 1);
        float ls = logf(s) + m;
        int gr = row0 + r;
        if (gr < NNODES) {
#pragma unroll
            for (int q = 0; q < 5; q++)
                *(float4*)(out + (size_t)gr * NCLS + cb + q * 4) =
                    make_float4(lg[q * 4] - ls, lg[q * 4 + 1] - ls,
                                lg[q * 4 + 2] - ls, lg[q * 4 + 3] - ls);
        }
    }
}

// ---------------------------------------------------------------------------
extern "C" void kernel_launch(void* const* d_in, const int* in_sizes, int n_in,
                              void* d_out, int out_size) {
    const float* x        = (const float*)d_in[0];
    const int*   ei_raw   = (const int*)d_in[1];
    const float* w1a      = (const float*)d_in[2];
    const float* b1a      = (const float*)d_in[3];
    const float* w1b      = (const float*)d_in[4];
    const float* b1b      = (const float*)d_in[5];
    const float* w2a      = (const float*)d_in[6];
    const float* b2a      = (const float*)d_in[7];
    const float* w2b      = (const float*)d_in[8];
    const float* b2b      = (const float*)d_in[9];
    const float* wfc      = (const float*)d_in[10];
    const float* bfc      = (const float*)d_in[11];
    float* out            = (float*)d_out;

    float *h1;
    unsigned short *preh, *prel, *wcvt;
    int *csr, *deg, *off, *cur, *bsum;
    cudaGetSymbolAddress((void**)&h1, g_h1);
    cudaGetSymbolAddress((void**)&preh, g_preh);
    cudaGetSymbolAddress((void**)&prel, g_prel);
    cudaGetSymbolAddress((void**)&csr, g_csr);
    cudaGetSymbolAddress((void**)&deg, g_deg);
    cudaGetSymbolAddress((void**)&off, g_off);
    cudaGetSymbolAddress((void**)&cur, g_cur);
    cudaGetSymbolAddress((void**)&bsum, g_bsum);
    cudaGetSymbolAddress((void**)&wcvt, g_wcvt);

    cudaFuncSetAttribute(mlp_mma_kernel,
                         cudaFuncAttributeMaxDynamicSharedMemorySize, S_TOTAL);

    const int egrid = (NEDGES + 255) / 256;
    const int agrid = (int)(((long long)NNODES * 32 + 255) / 256);
    const int mgrid = (NNODES + TM - 1) / TM;

    // --- CSR build + weight prep (prep also zeroes deg; launch index 0) ---
    prep_w_kernel<<<(DF * DF + 255) / 256, 256>>>(w1a, w1b, w2a, w2b, wcvt, deg);
    hist_kernel<<<egrid, 256>>>(ei_raw, deg);
    scan_part_kernel<<<NB_SCAN, 256>>>(deg, bsum);
    scan_write_kernel<<<NB_SCAN, 256>>>(deg, bsum, off, cur);
    scatter_kernel<<<egrid, 256>>>(ei_raw, cur, csr);

    // Layer 1 (agg is launch index 5 -> captured by ncu -s 5 -c 1)
    agg_kernel<<<agrid, 256>>>(x, x, off, csr, preh, prel);
    mlp_mma_kernel<<<mgrid, 256, S_TOTAL>>>(preh, prel, wcvt, b1a, b1b,
                                            nullptr, nullptr, h1);
    // Layer 2 (+ fused FC/log_softmax)
    agg_kernel<<<agrid, 256>>>(h1, h1, off, csr, preh, prel);
    mlp_mma_kernel<<<mgrid, 256, S_TOTAL>>>(preh, prel, wcvt + 4 * DF * DF, b2a, b2b,
                                            wfc, bfc, out);
}